// round 7
// baseline (speedup 1.0000x reference)
#include <cuda_runtime.h>
#include <cuda_fp16.h>
#include <stdint.h>

// ---------------- problem constants ----------------
#define BS    256
#define SEQ   4096
#define DD    128
#define NCATS 256
#define GCOLS 384

// ---------------- device scratch ----------------
__device__ __half g_Hh[(size_t)BS * SEQ * DD];   // hidden history, fp16 (for logits GEMM)
__device__ float  g_proj4[257 * DD * 4];         // per-token xi: [tok][d][{xr,xz,xn,0}]
__device__ __half g_WcT[NCATS * DD];             // W_cls transposed -> [cat][d], fp16
__device__ int    g_is64;

// ---------------- helpers ----------------
__device__ __forceinline__ uint32_t smem_u32(const void* p) {
    uint32_t a;
    asm("{ .reg .u64 t; cvta.to.shared.u64 t, %1; cvt.u32.u64 %0, t; }" : "=r"(a) : "l"(p));
    return a;
}
__device__ __forceinline__ uint32_t packh2(float a, float b) {
    __half2 h = __floats2half2_rn(a, b);
    return *reinterpret_cast<uint32_t*>(&h);
}
__device__ __forceinline__ void mma16816(float* d, const uint32_t* a, const uint32_t* b) {
    asm volatile(
        "mma.sync.aligned.m16n8k16.row.col.f32.f16.f16.f32 "
        "{%0,%1,%2,%3}, {%4,%5,%6,%7}, {%8,%9}, {%0,%1,%2,%3};\n"
        : "+f"(d[0]), "+f"(d[1]), "+f"(d[2]), "+f"(d[3])
        : "r"(a[0]), "r"(a[1]), "r"(a[2]), "r"(a[3]), "r"(b[0]), "r"(b[1]));
}
__device__ __forceinline__ void ldsm_x4(uint32_t* r, uint32_t addr) {
    asm volatile("ldmatrix.sync.aligned.m8n8.x4.shared.b16 {%0,%1,%2,%3}, [%4];"
                 : "=r"(r[0]), "=r"(r[1]), "=r"(r[2]), "=r"(r[3]) : "r"(addr));
}
__device__ __forceinline__ float ex2f(float x) {
    float y; asm("ex2.approx.f32 %0, %1;" : "=f"(y) : "f"(x)); return y;
}
__device__ __forceinline__ float rcpf(float x) {
    float y; asm("rcp.approx.f32 %0, %1;" : "=f"(y) : "f"(x)); return y;
}
__device__ __forceinline__ float sigf(float x) {
    return rcpf(1.f + ex2f(-1.4426950408889634f * x));
}
__device__ __forceinline__ float tanhf_fast(float x) {
    return 1.f - 2.f * rcpf(1.f + ex2f(2.8853900817779268f * x));
}

// ---------------- kernel 1: int64/int32 detection ----------------
__global__ void detect_kernel(const unsigned int* xw) {
    __shared__ unsigned int s[256];
    unsigned int v = 0;
    for (int i = threadIdx.x; i < 4096; i += 256) v |= xw[2 * i + 1];
    s[threadIdx.x] = v;
    __syncthreads();
    if (threadIdx.x == 0) {
        unsigned int a = 0;
        for (int i = 0; i < 256; i++) a |= s[i];
        g_is64 = (a == 0) ? 1 : 0;
    }
}

// ---------------- kernel 2: proj4[c][d] = (xr, xz, xn, 0) ----------------
__global__ void __launch_bounds__(DD) proj_kernel(const float* __restrict__ emb,
                                                  const float* __restrict__ Wi,
                                                  const float* __restrict__ bi) {
    __shared__ float e[DD];
    const int c = blockIdx.x;
    const int j = threadIdx.x;
    e[j] = emb[c * DD + j];
    __syncthreads();
    float a0 = bi[j], a1 = bi[DD + j], a2 = bi[2 * DD + j];
#pragma unroll 8
    for (int k = 0; k < DD; k++) {
        float ek = e[k];
        a0 += ek * Wi[k * GCOLS + j];
        a1 += ek * Wi[k * GCOLS + DD + j];
        a2 += ek * Wi[k * GCOLS + 2 * DD + j];
    }
    float4* o = (float4*)&g_proj4[(size_t)(c * DD + j) * 4];
    *o = make_float4(a0, a1, a2, 0.f);
}

// ---------------- kernel 2b: W_cls -> fp16 transposed ----------------
__global__ void prep_wc(const float* __restrict__ Wcls) {
    int i = blockIdx.x * 256 + threadIdx.x;      // 32768
    int d = i / NCATS, c = i % NCATS;
    g_WcT[c * DD + d] = __float2half_rn(Wcls[d * NCATS + c]);
}

// ---------------- kernel 3: HMMA GRU scan, 128 CTAs x 2 rows ----------------
// Warp w owns d-range [16w, 16w+16): computes r,z,n pre-activations for its own
// dims, gates entirely in registers (quad shuffle distributes the 4 valid
// (d,row) sets), double-buffered hT -> ONE __syncthreads per step.
#define HTP 136   // padded hT row (halves) -> 272B stride, conflict-free
__global__ void __launch_bounds__(256, 1)
scan_kernel(const int* __restrict__ xw,
            const float* __restrict__ Whrz,
            const float* __restrict__ Whn,
            const float* __restrict__ bhn,
            const float* __restrict__ initst) {
    __shared__ __half hT[2][8][HTP];    // double-buffered B operand (rows 2..7 stay 0)

    const int tid = threadIdx.x;
    const int w = tid >> 5, l = tid & 31;
    const int row0 = blockIdx.x * 2;
    const int gr = l >> 2, q = l & 3;
    const int d   = w * 16 + gr + ((q & 2) ? 8 : 0);  // this lane's gate dim
    const int row = q & 1;                            // this lane's batch row (0/1)

    // ---- build A fragments in registers: warp w holds r,z,n tiles for d-range ----
    // s=0: Whrz cols [16w,16w+16)  (r)
    // s=1: Whrz cols [128+16w, ..) (z)
    // s=2: Whn  cols [16w,16w+16)  (n)
    uint32_t A[3][8][4];
    {
        const int kc = q * 2;
#pragma unroll
        for (int s = 0; s < 3; s++) {
#pragma unroll
            for (int kt = 0; kt < 8; kt++) {
                const int k0 = kt * 16 + kc;
                float a00, a01, a10, a11, a20, a21, a30, a31;
                if (s == 2) {
                    int ga = w * 16 + gr, gb = ga + 8;
                    a00 = Whn[k0 * DD + ga];       a01 = Whn[(k0 + 1) * DD + ga];
                    a10 = Whn[k0 * DD + gb];       a11 = Whn[(k0 + 1) * DD + gb];
                    a20 = Whn[(k0 + 8) * DD + ga]; a21 = Whn[(k0 + 9) * DD + ga];
                    a30 = Whn[(k0 + 8) * DD + gb]; a31 = Whn[(k0 + 9) * DD + gb];
                } else {
                    int ga = s * 128 + w * 16 + gr, gb = ga + 8;
                    a00 = Whrz[k0 * 256 + ga];       a01 = Whrz[(k0 + 1) * 256 + ga];
                    a10 = Whrz[k0 * 256 + gb];       a11 = Whrz[(k0 + 1) * 256 + gb];
                    a20 = Whrz[(k0 + 8) * 256 + ga]; a21 = Whrz[(k0 + 9) * 256 + ga];
                    a30 = Whrz[(k0 + 8) * 256 + gb]; a31 = Whrz[(k0 + 9) * 256 + gb];
                }
                A[s][kt][0] = packh2(a00, a01);
                A[s][kt][1] = packh2(a10, a11);
                A[s][kt][2] = packh2(a20, a21);
                A[s][kt][3] = packh2(a30, a31);
            }
        }
    }

    // ---- init: zero both hT buffers, write h0, preload xi(BOS)/token ----
    for (int i = tid; i < 2 * 8 * HTP; i += 256) ((__half*)hT)[i] = __float2half(0.f);
    __syncthreads();
    float h  = initst[d];
    const float bn = bhn[d];
    hT[0][row][d] = __float2half_rn(h);
    float4 xi = *(const float4*)&g_proj4[(size_t)(NCATS * DD + d) * 4];   // BOS
    const int is64 = g_is64;
    const int xbase = (row0 + row) * SEQ;
    int tok = is64 ? xw[2 * xbase] : xw[xbase];

    const char* hb0 = (const char*)&hT[0][gr][0] + q * 4;   // this lane's B-row base

    for (int t = 0; t < SEQ; t++) {
        __syncthreads();   // hT[t&1] complete (written as "next" in prev step)

        // ---- load all B fragments up front (conflict-free) ----
        const char* hb = hb0 + (t & 1) * (8 * HTP * 2);
        uint32_t b[8][2];
#pragma unroll
        for (int kt = 0; kt < 8; kt++) {
            b[kt][0] = *(const uint32_t*)(hb + kt * 32);
            b[kt][1] = *(const uint32_t*)(hb + kt * 32 + 16);
        }

        // ---- 24 MMAs: r,z,n pre-activations for this warp's 16 dims, 2 rows ----
        float acc[3][4];
#pragma unroll
        for (int s = 0; s < 3; s++)
#pragma unroll
            for (int p = 0; p < 4; p++) acc[s][p] = 0.f;
#pragma unroll
        for (int kt = 0; kt < 8; kt++)
#pragma unroll
            for (int s = 0; s < 3; s++) mma16816(acc[s], A[s][kt], b[kt]);

        // ---- prefetch next xi / token in the MMA drain shadow ----
        float4 xin = *(const float4*)&g_proj4[(size_t)(tok * DD + d) * 4];
        int tokn = tok;
        if (t + 1 < SEQ) {
            int idx = xbase + t + 1;
            tokn = is64 ? xw[2 * idx] : xw[idx];
        }

        // ---- quad shuffle: distribute the 4 valid (d,row) sets across lanes ----
        const int src = l & ~3;
        float pr, pz, pn;
        {
            float v0 = __shfl_sync(0xffffffffu, acc[0][0], src);
            float v1 = __shfl_sync(0xffffffffu, acc[0][1], src);
            float v2 = __shfl_sync(0xffffffffu, acc[0][2], src);
            float v3 = __shfl_sync(0xffffffffu, acc[0][3], src);
            pr = (q == 0) ? v0 : (q == 1) ? v1 : (q == 2) ? v2 : v3;
            v0 = __shfl_sync(0xffffffffu, acc[1][0], src);
            v1 = __shfl_sync(0xffffffffu, acc[1][1], src);
            v2 = __shfl_sync(0xffffffffu, acc[1][2], src);
            v3 = __shfl_sync(0xffffffffu, acc[1][3], src);
            pz = (q == 0) ? v0 : (q == 1) ? v1 : (q == 2) ? v2 : v3;
            v0 = __shfl_sync(0xffffffffu, acc[2][0], src);
            v1 = __shfl_sync(0xffffffffu, acc[2][1], src);
            v2 = __shfl_sync(0xffffffffu, acc[2][2], src);
            v3 = __shfl_sync(0xffffffffu, acc[2][3], src);
            pn = (q == 0) ? v0 : (q == 1) ? v1 : (q == 2) ? v2 : v3;
        }

        // ---- gates (one set per lane, exact R6 math) ----
        float R = sigf(xi.x + pr);
        float Z = sigf(xi.y + pz);
        float N = tanhf_fast(xi.z + R * (pn + bn));
        h = N + Z * (h - N);

        __half hh = __float2half_rn(h);
        g_Hh[((size_t)(row0 + row) * SEQ + t) * DD + d] = hh;
        hT[(t + 1) & 1][row][d] = hh;      // write NEXT buffer: no WAR vs readers
        xi = xin; tok = tokn;
    }
}

// ---------------- kernel 4: logits = H @ W_cls + b_cls via HMMA ----------------
#define HPAD 136
__global__ void __launch_bounds__(256, 1) logits_kernel(const float* __restrict__ bcls,
                                                        float* __restrict__ out) {
    extern __shared__ __half sh[];
    __half* Hs = sh;                    // [128][HPAD]
    __half* Wc = sh + 128 * HPAD;       // [256][HPAD]  (WcT: [cat][d])
    const int tid = threadIdx.x;
    const int batch = blockIdx.y;
    const int t0 = blockIdx.x * 128;

    const __half* hsrc = &g_Hh[((size_t)batch * SEQ + t0) * DD];
    for (int i = tid; i < 128 * 16; i += 256) {
        int rr = i >> 4, c8 = (i & 15) * 8;
        *(float4*)&Hs[rr * HPAD + c8] = *(const float4*)&hsrc[rr * DD + c8];
    }
    for (int i = tid; i < 256 * 16; i += 256) {
        int rr = i >> 4, c8 = (i & 15) * 8;
        *(float4*)&Wc[rr * HPAD + c8] = *(const float4*)&g_WcT[rr * DD + c8];
    }
    __syncthreads();

    const int w = tid >> 5, l = tid & 31;
    const int m0 = (w >> 2) * 64;
    const int n0 = (w & 3) * 64;

    float acc[4][8][4];
#pragma unroll
    for (int nt = 0; nt < 8; nt++) {
        float b0 = bcls[n0 + nt * 8 + (l & 3) * 2];
        float b1 = bcls[n0 + nt * 8 + (l & 3) * 2 + 1];
#pragma unroll
        for (int mt = 0; mt < 4; mt++) {
            acc[mt][nt][0] = b0; acc[mt][nt][1] = b1;
            acc[mt][nt][2] = b0; acc[mt][nt][3] = b1;
        }
    }

    const uint32_t hs_u32 = smem_u32(Hs);
    const int arow = m0 + (l & 15);
    const int acol = (l >> 4) * 8;
#pragma unroll
    for (int kt = 0; kt < 8; kt++) {
        uint32_t Af[4][4];
#pragma unroll
        for (int mt = 0; mt < 4; mt++)
            ldsm_x4(Af[mt], hs_u32 + (uint32_t)(((arow + mt * 16) * HPAD + kt * 16 + acol) * 2));
        uint32_t Bf[8][2];
#pragma unroll
        for (int nt = 0; nt < 8; nt++) {
            const __half* wp = &Wc[(n0 + nt * 8 + (l >> 2)) * HPAD + kt * 16 + (l & 3) * 2];
            Bf[nt][0] = *(const uint32_t*)wp;
            Bf[nt][1] = *(const uint32_t*)(wp + 8);
        }
#pragma unroll
        for (int mt = 0; mt < 4; mt++)
#pragma unroll
            for (int nt = 0; nt < 8; nt++) mma16816(acc[mt][nt], Af[mt], Bf[nt]);
    }

    const size_t obase = ((size_t)batch * SEQ + t0) * NCATS;
#pragma unroll
    for (int mt = 0; mt < 4; mt++) {
        const int rrow = m0 + mt * 16 + (l >> 2);
#pragma unroll
        for (int nt = 0; nt < 8; nt++) {
            const int col = n0 + nt * 8 + (l & 3) * 2;
            *(float2*)&out[obase + (size_t)rrow * NCATS + col] =
                make_float2(acc[mt][nt][0], acc[mt][nt][1]);
            *(float2*)&out[obase + (size_t)(rrow + 8) * NCATS + col] =
                make_float2(acc[mt][nt][2], acc[mt][nt][3]);
        }
    }
}

// ---------------- launch ----------------
extern "C" void kernel_launch(void* const* d_in, const int* in_sizes, int n_in,
                              void* d_out, int out_size) {
    const void*  x      = d_in[0];
    const float* emb    = (const float*)d_in[1];
    const float* Wi     = (const float*)d_in[2];
    const float* bi     = (const float*)d_in[3];
    const float* Whrz   = (const float*)d_in[4];
    const float* Whn    = (const float*)d_in[5];
    const float* bhn    = (const float*)d_in[6];
    const float* Wcls   = (const float*)d_in[7];
    const float* bcls   = (const float*)d_in[8];
    const float* initst = (const float*)d_in[9];
    float* out = (float*)d_out;

    const int LOG_SMEM = (128 + 256) * HPAD * (int)sizeof(__half);   // 104448 B
    cudaFuncSetAttribute(logits_kernel, cudaFuncAttributeMaxDynamicSharedMemorySize, LOG_SMEM);

    detect_kernel<<<1, 256>>>((const unsigned int*)x);
    proj_kernel<<<257, DD>>>(emb, Wi, bi);
    prep_wc<<<(NCATS * DD) / 256, 256>>>(Wcls);
    scan_kernel<<<BS / 2, 256>>>((const int*)x, Whrz, Whn, bhn, initst);
    logits_kernel<<<dim3(SEQ / 128, BS), 256, LOG_SMEM>>>(bcls, out);
}

// round 11
// speedup vs baseline: 2.1886x; 2.1886x over previous
#include <cuda_runtime.h>
#include <cuda_fp16.h>
#include <stdint.h>

// ---------------- problem constants ----------------
#define BS    256
#define SEQ   4096
#define DD    128
#define NCATS 256
#define GCOLS 384

// ---------------- device scratch ----------------
__device__ __half g_Hh[(size_t)BS * SEQ * DD];   // hidden history, fp16 (for logits GEMM)
__device__ float  g_proj4[257 * DD * 4];         // per-token xi: [tok][d][{xr,xz,xn,0}]
__device__ __half g_WcT[NCATS * DD];             // W_cls transposed -> [cat][d], fp16
__device__ int    g_is64;

// ---------------- helpers ----------------
__device__ __forceinline__ uint32_t smem_u32(const void* p) {
    uint32_t a;
    asm("{ .reg .u64 t; cvta.to.shared.u64 t, %1; cvt.u32.u64 %0, t; }" : "=r"(a) : "l"(p));
    return a;
}
__device__ __forceinline__ uint32_t packh2(float a, float b) {
    __half2 h = __floats2half2_rn(a, b);
    return *reinterpret_cast<uint32_t*>(&h);
}
__device__ __forceinline__ void mma16816(float* d, const uint32_t* a, const uint32_t* b) {
    asm volatile(
        "mma.sync.aligned.m16n8k16.row.col.f32.f16.f16.f32 "
        "{%0,%1,%2,%3}, {%4,%5,%6,%7}, {%8,%9}, {%0,%1,%2,%3};\n"
        : "+f"(d[0]), "+f"(d[1]), "+f"(d[2]), "+f"(d[3])
        : "r"(a[0]), "r"(a[1]), "r"(a[2]), "r"(a[3]), "r"(b[0]), "r"(b[1]));
}
__device__ __forceinline__ void ldsm_x4(uint32_t* r, uint32_t addr) {
    asm volatile("ldmatrix.sync.aligned.m8n8.x4.shared.b16 {%0,%1,%2,%3}, [%4];"
                 : "=r"(r[0]), "=r"(r[1]), "=r"(r[2]), "=r"(r[3]) : "r"(addr));
}
__device__ __forceinline__ float ex2f(float x) {
    float y; asm("ex2.approx.f32 %0, %1;" : "=f"(y) : "f"(x)); return y;
}
__device__ __forceinline__ float rcpf(float x) {
    float y; asm("rcp.approx.f32 %0, %1;" : "=f"(y) : "f"(x)); return y;
}
__device__ __forceinline__ float sigf(float x) {
    return rcpf(1.f + ex2f(-1.4426950408889634f * x));
}
__device__ __forceinline__ float tanhf_fast(float x) {
    return 1.f - 2.f * rcpf(1.f + ex2f(2.8853900817779268f * x));
}

// ---------------- kernel 1: int64/int32 detection ----------------
__global__ void detect_kernel(const unsigned int* xw) {
    __shared__ unsigned int s[256];
    unsigned int v = 0;
    for (int i = threadIdx.x; i < 4096; i += 256) v |= xw[2 * i + 1];
    s[threadIdx.x] = v;
    __syncthreads();
    if (threadIdx.x == 0) {
        unsigned int a = 0;
        for (int i = 0; i < 256; i++) a |= s[i];
        g_is64 = (a == 0) ? 1 : 0;
    }
}

// ---------------- kernel 2: proj4[c][d] = (xr, xz, xn, 0) ----------------
__global__ void __launch_bounds__(DD) proj_kernel(const float* __restrict__ emb,
                                                  const float* __restrict__ Wi,
                                                  const float* __restrict__ bi) {
    __shared__ float e[DD];
    const int c = blockIdx.x;
    const int j = threadIdx.x;
    e[j] = emb[c * DD + j];
    __syncthreads();
    float a0 = bi[j], a1 = bi[DD + j], a2 = bi[2 * DD + j];
#pragma unroll 8
    for (int k = 0; k < DD; k++) {
        float ek = e[k];
        a0 += ek * Wi[k * GCOLS + j];
        a1 += ek * Wi[k * GCOLS + DD + j];
        a2 += ek * Wi[k * GCOLS + 2 * DD + j];
    }
    float4* o = (float4*)&g_proj4[(size_t)(c * DD + j) * 4];
    *o = make_float4(a0, a1, a2, 0.f);
}

// ---------------- kernel 2b: W_cls -> fp16 transposed ----------------
__global__ void prep_wc(const float* __restrict__ Wcls) {
    int i = blockIdx.x * 256 + threadIdx.x;      // 32768
    int d = i / NCATS, c = i % NCATS;
    g_WcT[c * DD + d] = __float2half_rn(Wcls[d * NCATS + c]);
}

// ---------------- kernel 3: HMMA GRU scan, 128 CTAs x 2 rows (R6 + acc split) ----------------
#define HTP 136   // padded hT row (halves) -> 272B stride, conflict-free
__global__ void __launch_bounds__(256, 1)
scan_kernel(const int* __restrict__ xw,
            const float* __restrict__ Whrz,
            const float* __restrict__ Whn,
            const float* __restrict__ bhn,
            const float* __restrict__ initst) {
    __shared__ __half hT[8][HTP];       // B operand: [n][k], rows 2..7 stay zero
    __shared__ float  gbuf[GCOLS][2];   // MMA results [gate][row]

    const int tid = threadIdx.x;
    const int w = tid >> 5, l = tid & 31;
    const int row0 = blockIdx.x * 2;
    const int d = tid & 127, r = tid >> 7;    // gate-phase mapping (1 set/thread)

    // ---- build A fragments in registers: G[g][k] = W[k][g], fp16 ----
    uint32_t A[3][8][4];
    {
        const int gr = l >> 2;             // 0..7
        const int kc = (l & 3) * 2;        // 0,2,4,6
#pragma unroll
        for (int s = 0; s < 3; s++) {
            const int g0 = (w * 3 + s) * 16;
#pragma unroll
            for (int kt = 0; kt < 8; kt++) {
                const int k0 = kt * 16 + kc;
                int ga = g0 + gr, gb = g0 + gr + 8;
                float a00, a01, a10, a11, a20, a21, a30, a31;
                if (ga < 256) { a00 = Whrz[k0 * 256 + ga];       a01 = Whrz[(k0 + 1) * 256 + ga];
                                a20 = Whrz[(k0 + 8) * 256 + ga]; a21 = Whrz[(k0 + 9) * 256 + ga]; }
                else          { int gg = ga - 256;
                                a00 = Whn[k0 * DD + gg];         a01 = Whn[(k0 + 1) * DD + gg];
                                a20 = Whn[(k0 + 8) * DD + gg];   a21 = Whn[(k0 + 9) * DD + gg]; }
                if (gb < 256) { a10 = Whrz[k0 * 256 + gb];       a11 = Whrz[(k0 + 1) * 256 + gb];
                                a30 = Whrz[(k0 + 8) * 256 + gb]; a31 = Whrz[(k0 + 9) * 256 + gb]; }
                else          { int gg = gb - 256;
                                a10 = Whn[k0 * DD + gg];         a11 = Whn[(k0 + 1) * DD + gg];
                                a30 = Whn[(k0 + 8) * DD + gg];   a31 = Whn[(k0 + 9) * DD + gg]; }
                A[s][kt][0] = packh2(a00, a01);
                A[s][kt][1] = packh2(a10, a11);
                A[s][kt][2] = packh2(a20, a21);
                A[s][kt][3] = packh2(a30, a31);
            }
        }
    }

    // ---- init hT (zero padding rows), h, xi(BOS), first token ----
    for (int i = tid; i < 8 * HTP; i += 256) ((__half*)hT)[i] = __float2half(0.f);
    __syncthreads();
    float h = initst[d];
    const float bn = bhn[d];
    hT[r][d] = __float2half_rn(h);
    float4 xi = *(const float4*)&g_proj4[(size_t)(NCATS * DD + d) * 4];   // BOS
    const int is64 = g_is64;
    const int xbase = (row0 + r) * SEQ;
    int tok = is64 ? xw[2 * xbase] : xw[xbase];

    const uint32_t bRow = (uint32_t)((l >> 2) * HTP * 2);   // byte offset of this lane's B row
    const uint32_t bCol = (uint32_t)((l & 3) * 4);          // 2 halves

    for (int t = 0; t < SEQ; t++) {
        __syncthreads();   // hT(t) ready

        // ---- MMA phase: D[384x2] = G @ h, 6 independent accumulation chains ----
        float acc[3][2][4];
#pragma unroll
        for (int s = 0; s < 3; s++)
#pragma unroll
            for (int p = 0; p < 4; p++) { acc[s][0][p] = 0.f; acc[s][1][p] = 0.f; }

        const char* hbase = (const char*)hT + bRow + bCol;
#pragma unroll
        for (int kt = 0; kt < 8; kt++) {
            uint32_t b[2];
            b[0] = *(const uint32_t*)(hbase + kt * 32);
            b[1] = *(const uint32_t*)(hbase + kt * 32 + 16);
#pragma unroll
            for (int s = 0; s < 3; s++) mma16816(acc[s][kt & 1], A[s][kt], b);
        }
        if ((l & 3) == 0) {
            const int gr = l >> 2;
#pragma unroll
            for (int s = 0; s < 3; s++) {
                const int g = (w * 3 + s) * 16 + gr;
                *(float2*)&gbuf[g][0]     = make_float2(acc[s][0][0] + acc[s][1][0],
                                                        acc[s][0][1] + acc[s][1][1]);
                *(float2*)&gbuf[g + 8][0] = make_float2(acc[s][0][2] + acc[s][1][2],
                                                        acc[s][0][3] + acc[s][1][3]);
            }
        }
        __syncthreads();

        // ---- gates: one (d, row) pair per thread ----
        float hr = gbuf[d][r], hz = gbuf[DD + d][r], hnp = gbuf[2 * DD + d][r];

        // prefetch next xi / token (overlaps with MUFU chain)
        float4 xin = *(const float4*)&g_proj4[(size_t)(tok * DD + d) * 4];
        int tokn = tok;
        if (t + 1 < SEQ) {
            int idx = xbase + t + 1;
            tokn = is64 ? xw[2 * idx] : xw[idx];
        }

        float R = sigf(xi.x + hr);
        float Z = sigf(xi.y + hz);
        float N = tanhf_fast(xi.z + R * (hnp + bn));
        h = N + Z * (h - N);

        g_Hh[((size_t)(row0 + r) * SEQ + t) * DD + d] = __float2half_rn(h);
        hT[r][d] = __float2half_rn(h);
        xi = xin; tok = tokn;
    }
}

// ---------------- kernel 4: logits = H @ W_cls + b_cls via HMMA ----------------
// 512 threads, 16 warps in 4x4: warp tile 32 rows x 64 cats. 25% occupancy.
#define HPAD 136
__global__ void __launch_bounds__(512, 1) logits_kernel(const float* __restrict__ bcls,
                                                        float* __restrict__ out) {
    extern __shared__ __half sh[];
    __half* Hs = sh;                    // [128][HPAD]
    __half* Wc = sh + 128 * HPAD;       // [256][HPAD]  (WcT: [cat][d])
    const int tid = threadIdx.x;
    const int batch = blockIdx.y;
    const int t0 = blockIdx.x * 128;

    const __half* hsrc = &g_Hh[((size_t)batch * SEQ + t0) * DD];
    for (int i = tid; i < 128 * 16; i += 512) {
        int rr = i >> 4, c8 = (i & 15) * 8;
        *(float4*)&Hs[rr * HPAD + c8] = *(const float4*)&hsrc[rr * DD + c8];
    }
    for (int i = tid; i < 256 * 16; i += 512) {
        int rr = i >> 4, c8 = (i & 15) * 8;
        *(float4*)&Wc[rr * HPAD + c8] = *(const float4*)&g_WcT[rr * DD + c8];
    }
    __syncthreads();

    const int w = tid >> 5, l = tid & 31;
    const int m0 = (w >> 2) * 32;       // 4 m-groups of 32 rows
    const int n0 = (w & 3) * 64;        // 4 n-groups of 64 cats

    float acc[2][8][4];
#pragma unroll
    for (int nt = 0; nt < 8; nt++) {
        float b0 = bcls[n0 + nt * 8 + (l & 3) * 2];
        float b1 = bcls[n0 + nt * 8 + (l & 3) * 2 + 1];
#pragma unroll
        for (int mt = 0; mt < 2; mt++) {
            acc[mt][nt][0] = b0; acc[mt][nt][1] = b1;
            acc[mt][nt][2] = b0; acc[mt][nt][3] = b1;
        }
    }

    const uint32_t hs_u32 = smem_u32(Hs);
    const int arow = m0 + (l & 15);
    const int acol = (l >> 4) * 8;
#pragma unroll
    for (int kt = 0; kt < 8; kt++) {
        uint32_t Af[2][4];
#pragma unroll
        for (int mt = 0; mt < 2; mt++)
            ldsm_x4(Af[mt], hs_u32 + (uint32_t)(((arow + mt * 16) * HPAD + kt * 16 + acol) * 2));
        uint32_t Bf[8][2];
#pragma unroll
        for (int nt = 0; nt < 8; nt++) {
            const __half* wp = &Wc[(n0 + nt * 8 + (l >> 2)) * HPAD + kt * 16 + (l & 3) * 2];
            Bf[nt][0] = *(const uint32_t*)wp;
            Bf[nt][1] = *(const uint32_t*)(wp + 8);
        }
#pragma unroll
        for (int mt = 0; mt < 2; mt++)
#pragma unroll
            for (int nt = 0; nt < 8; nt++) mma16816(acc[mt][nt], Af[mt], Bf[nt]);
    }

    const size_t obase = ((size_t)batch * SEQ + t0) * NCATS;
#pragma unroll
    for (int mt = 0; mt < 2; mt++) {
        const int rrow = m0 + mt * 16 + (l >> 2);
#pragma unroll
        for (int nt = 0; nt < 8; nt++) {
            const int col = n0 + nt * 8 + (l & 3) * 2;
            *(float2*)&out[obase + (size_t)rrow * NCATS + col] =
                make_float2(acc[mt][nt][0], acc[mt][nt][1]);
            *(float2*)&out[obase + (size_t)(rrow + 8) * NCATS + col] =
                make_float2(acc[mt][nt][2], acc[mt][nt][3]);
        }
    }
}

// ---------------- launch ----------------
extern "C" void kernel_launch(void* const* d_in, const int* in_sizes, int n_in,
                              void* d_out, int out_size) {
    const void*  x      = d_in[0];
    const float* emb    = (const float*)d_in[1];
    const float* Wi     = (const float*)d_in[2];
    const float* bi     = (const float*)d_in[3];
    const float* Whrz   = (const float*)d_in[4];
    const float* Whn    = (const float*)d_in[5];
    const float* bhn    = (const float*)d_in[6];
    const float* Wcls   = (const float*)d_in[7];
    const float* bcls   = (const float*)d_in[8];
    const float* initst = (const float*)d_in[9];
    float* out = (float*)d_out;

    const int LOG_SMEM = (128 + 256) * HPAD * (int)sizeof(__half);   // 104448 B
    cudaFuncSetAttribute(logits_kernel, cudaFuncAttributeMaxDynamicSharedMemorySize, LOG_SMEM);

    detect_kernel<<<1, 256>>>((const unsigned int*)x);
    proj_kernel<<<257, DD>>>(emb, Wi, bi);
    prep_wc<<<(NCATS * DD) / 256, 256>>>(Wcls);
    scan_kernel<<<BS / 2, 256>>>((const int*)x, Whrz, Whn, bhn, initst);
    logits_kernel<<<dim3(SEQ / 128, BS), 512, LOG_SMEM>>>(bcls, out);
}

// round 12
// speedup vs baseline: 2.2573x; 1.0314x over previous
#include <cuda_runtime.h>
#include <cuda_fp16.h>
#include <stdint.h>

// ---------------- problem constants ----------------
#define BS    256
#define SEQ   4096
#define DD    128
#define NCATS 256
#define GCOLS 384

// ---------------- device scratch ----------------
__device__ __half g_Hh[(size_t)BS * SEQ * DD];   // hidden history, fp16 (for logits GEMM)
__device__ float  g_proj4[257 * DD * 4];         // per-token xi: [tok][d][{xr,xz,xn,0}]
__device__ __half g_WcT[NCATS * DD];             // W_cls transposed -> [cat][d], fp16
__device__ int    g_is64;

// ---------------- helpers ----------------
__device__ __forceinline__ uint32_t smem_u32(const void* p) {
    uint32_t a;
    asm("{ .reg .u64 t; cvta.to.shared.u64 t, %1; cvt.u32.u64 %0, t; }" : "=r"(a) : "l"(p));
    return a;
}
__device__ __forceinline__ uint32_t packh2(float a, float b) {
    __half2 h = __floats2half2_rn(a, b);
    return *reinterpret_cast<uint32_t*>(&h);
}
__device__ __forceinline__ void mma16816(float* d, const uint32_t* a, const uint32_t* b) {
    asm volatile(
        "mma.sync.aligned.m16n8k16.row.col.f32.f16.f16.f32 "
        "{%0,%1,%2,%3}, {%4,%5,%6,%7}, {%8,%9}, {%0,%1,%2,%3};\n"
        : "+f"(d[0]), "+f"(d[1]), "+f"(d[2]), "+f"(d[3])
        : "r"(a[0]), "r"(a[1]), "r"(a[2]), "r"(a[3]), "r"(b[0]), "r"(b[1]));
}
__device__ __forceinline__ void ldsm_x4(uint32_t* r, uint32_t addr) {
    asm volatile("ldmatrix.sync.aligned.m8n8.x4.shared.b16 {%0,%1,%2,%3}, [%4];"
                 : "=r"(r[0]), "=r"(r[1]), "=r"(r[2]), "=r"(r[3]) : "r"(addr));
}
__device__ __forceinline__ float ex2f(float x) {
    float y; asm("ex2.approx.f32 %0, %1;" : "=f"(y) : "f"(x)); return y;
}
__device__ __forceinline__ float rcpf(float x) {
    float y; asm("rcp.approx.f32 %0, %1;" : "=f"(y) : "f"(x)); return y;
}
__device__ __forceinline__ float sigf(float x) {
    return rcpf(1.f + ex2f(-1.4426950408889634f * x));
}
__device__ __forceinline__ float tanhf_fast(float x) {
    return 1.f - 2.f * rcpf(1.f + ex2f(2.8853900817779268f * x));
}

// ---------------- kernel 1: int64/int32 detection ----------------
__global__ void detect_kernel(const unsigned int* xw) {
    __shared__ unsigned int s[256];
    unsigned int v = 0;
    for (int i = threadIdx.x; i < 4096; i += 256) v |= xw[2 * i + 1];
    s[threadIdx.x] = v;
    __syncthreads();
    if (threadIdx.x == 0) {
        unsigned int a = 0;
        for (int i = 0; i < 256; i++) a |= s[i];
        g_is64 = (a == 0) ? 1 : 0;
    }
}

// ---------------- kernel 2: proj4[c][d] = (xr, xz, xn, 0) ----------------
__global__ void __launch_bounds__(DD) proj_kernel(const float* __restrict__ emb,
                                                  const float* __restrict__ Wi,
                                                  const float* __restrict__ bi) {
    __shared__ float e[DD];
    const int c = blockIdx.x;
    const int j = threadIdx.x;
    e[j] = emb[c * DD + j];
    __syncthreads();
    float a0 = bi[j], a1 = bi[DD + j], a2 = bi[2 * DD + j];
#pragma unroll 8
    for (int k = 0; k < DD; k++) {
        float ek = e[k];
        a0 += ek * Wi[k * GCOLS + j];
        a1 += ek * Wi[k * GCOLS + DD + j];
        a2 += ek * Wi[k * GCOLS + 2 * DD + j];
    }
    float4* o = (float4*)&g_proj4[(size_t)(c * DD + j) * 4];
    *o = make_float4(a0, a1, a2, 0.f);
}

// ---------------- kernel 2b: W_cls -> fp16 transposed ----------------
__global__ void prep_wc(const float* __restrict__ Wcls) {
    int i = blockIdx.x * 256 + threadIdx.x;      // 32768
    int d = i / NCATS, c = i % NCATS;
    g_WcT[c * DD + d] = __float2half_rn(Wcls[d * NCATS + c]);
}

// ---------------- kernel 3: HMMA GRU scan, 128 CTAs x 2 rows ----------------
// Warp w owns r,z,n for d in [16w,16w+16). B n-column -> physical row (n&1):
// every lane's own D fragment holds both batch rows for its 2 gate-dims, so the
// epilogue is a register select (no gbuf, no shuffles). Double-buffered 2-row hT
// -> ONE __syncthreads per step.
#define HTP 136   // padded hT row (halves) -> 272B stride
__global__ void __launch_bounds__(256, 1)
scan_kernel(const int* __restrict__ xw,
            const float* __restrict__ Whrz,
            const float* __restrict__ Whn,
            const float* __restrict__ bhn,
            const float* __restrict__ initst) {
    __shared__ __half hT[2][2][HTP];    // [buf][row][k]

    const int tid = threadIdx.x;
    const int w = tid >> 5, l = tid & 31;
    const int gr = l >> 2, q = l & 3;
    const int row0 = blockIdx.x * 2;
    const int d   = w * 16 + gr + ((q & 2) ? 8 : 0);  // this lane's gate dim
    const int row = q & 1;                            // this lane's batch row

    // ---- A fragments (R7-validated remap): warp w holds r,z,n for its d-range ----
    uint32_t A[3][8][4];
    {
        const int kc = q * 2;
#pragma unroll
        for (int s = 0; s < 3; s++) {
#pragma unroll
            for (int kt = 0; kt < 8; kt++) {
                const int k0 = kt * 16 + kc;
                float a00, a01, a10, a11, a20, a21, a30, a31;
                if (s == 2) {
                    int ga = w * 16 + gr, gb = ga + 8;
                    a00 = Whn[k0 * DD + ga];       a01 = Whn[(k0 + 1) * DD + ga];
                    a10 = Whn[k0 * DD + gb];       a11 = Whn[(k0 + 1) * DD + gb];
                    a20 = Whn[(k0 + 8) * DD + ga]; a21 = Whn[(k0 + 9) * DD + ga];
                    a30 = Whn[(k0 + 8) * DD + gb]; a31 = Whn[(k0 + 9) * DD + gb];
                } else {
                    int ga = s * 128 + w * 16 + gr, gb = ga + 8;
                    a00 = Whrz[k0 * 256 + ga];       a01 = Whrz[(k0 + 1) * 256 + ga];
                    a10 = Whrz[k0 * 256 + gb];       a11 = Whrz[(k0 + 1) * 256 + gb];
                    a20 = Whrz[(k0 + 8) * 256 + ga]; a21 = Whrz[(k0 + 9) * 256 + ga];
                    a30 = Whrz[(k0 + 8) * 256 + gb]; a31 = Whrz[(k0 + 9) * 256 + gb];
                }
                A[s][kt][0] = packh2(a00, a01);
                A[s][kt][1] = packh2(a10, a11);
                A[s][kt][2] = packh2(a20, a21);
                A[s][kt][3] = packh2(a30, a31);
            }
        }
    }

    // ---- init: h0 into hT buf0 (each lane covers its (row,d)), xi(BOS), token ----
    float h = initst[d];
    const float bn = bhn[d];
    hT[0][row][d] = __float2half_rn(h);
    float4 xi = *(const float4*)&g_proj4[(size_t)(NCATS * DD + d) * 4];   // BOS
    const int is64 = g_is64;
    const int xbase = (row0 + row) * SEQ;
    int tok = is64 ? xw[2 * xbase] : xw[xbase];
    __syncthreads();

    // lane's B-fragment base: n-col (l>>2) -> physical row (l>>2)&1 (broadcast)
    const uint32_t bOff = (uint32_t)(((l >> 2) & 1) * (HTP * 2) + q * 4);

    for (int t = 0; t < SEQ; t++) {
        // ---- B fragments from hT[t&1] ----
        const char* hb = (const char*)hT + (uint32_t)((t & 1) * (2 * HTP * 2)) + bOff;
        uint32_t b[8][2];
#pragma unroll
        for (int kt = 0; kt < 8; kt++) {
            b[kt][0] = *(const uint32_t*)(hb + kt * 32);
            b[kt][1] = *(const uint32_t*)(hb + kt * 32 + 16);
        }

        // ---- 24 MMAs, 6 independent chains ----
        float acc[3][2][4];
#pragma unroll
        for (int s = 0; s < 3; s++)
#pragma unroll
            for (int p = 0; p < 4; p++) { acc[s][0][p] = 0.f; acc[s][1][p] = 0.f; }
#pragma unroll
        for (int kt = 0; kt < 8; kt++)
#pragma unroll
            for (int s = 0; s < 3; s++) mma16816(acc[s][kt & 1], A[s][kt], b[kt]);

        // ---- prefetch next xi / token in the MMA drain shadow ----
        float4 xin = *(const float4*)&g_proj4[(size_t)(tok * DD + d) * 4];
        int tokn = tok;
        if (t + 1 < SEQ) {
            int idx = xbase + t + 1;
            tokn = is64 ? xw[2 * idx] : xw[idx];
        }

        // ---- register select of this lane's (d,row) pre-activations ----
        // D col 2q -> row0, col 2q+1 -> row1; acc idx: +2 selects m=gr+8
        float pr, pz, pn;
        {
            float e0, e1;
            e0 = (q & 2) ? acc[0][0][2] : acc[0][0][0];
            e1 = (q & 2) ? acc[0][0][3] : acc[0][0][1];
            pr = ((q & 1) ? e1 : e0);
            e0 = (q & 2) ? acc[0][1][2] : acc[0][1][0];
            e1 = (q & 2) ? acc[0][1][3] : acc[0][1][1];
            pr += ((q & 1) ? e1 : e0);

            e0 = (q & 2) ? acc[1][0][2] : acc[1][0][0];
            e1 = (q & 2) ? acc[1][0][3] : acc[1][0][1];
            pz = ((q & 1) ? e1 : e0);
            e0 = (q & 2) ? acc[1][1][2] : acc[1][1][0];
            e1 = (q & 2) ? acc[1][1][3] : acc[1][1][1];
            pz += ((q & 1) ? e1 : e0);

            e0 = (q & 2) ? acc[2][0][2] : acc[2][0][0];
            e1 = (q & 2) ? acc[2][0][3] : acc[2][0][1];
            pn = ((q & 1) ? e1 : e0);
            e0 = (q & 2) ? acc[2][1][2] : acc[2][1][0];
            e1 = (q & 2) ? acc[2][1][3] : acc[2][1][1];
            pn += ((q & 1) ? e1 : e0);
        }

        // ---- gates (identical math to R6/R11) ----
        float R = sigf(xi.x + pr);
        float Z = sigf(xi.y + pz);
        float N = tanhf_fast(xi.z + R * (pn + bn));
        h = N + Z * (h - N);

        __half hh = __float2half_rn(h);
        g_Hh[((size_t)(row0 + row) * SEQ + t) * DD + d] = hh;
        hT[(t + 1) & 1][row][d] = hh;      // write NEXT buffer
        xi = xin; tok = tokn;
        __syncthreads();                   // ONE barrier per step
    }
}

// ---------------- kernel 4: logits = H @ W_cls + b_cls via HMMA (R11) ----------------
#define HPAD 136
__global__ void __launch_bounds__(512, 1) logits_kernel(const float* __restrict__ bcls,
                                                        float* __restrict__ out) {
    extern __shared__ __half sh[];
    __half* Hs = sh;                    // [128][HPAD]
    __half* Wc = sh + 128 * HPAD;       // [256][HPAD]  (WcT: [cat][d])
    const int tid = threadIdx.x;
    const int batch = blockIdx.y;
    const int t0 = blockIdx.x * 128;

    const __half* hsrc = &g_Hh[((size_t)batch * SEQ + t0) * DD];
    for (int i = tid; i < 128 * 16; i += 512) {
        int rr = i >> 4, c8 = (i & 15) * 8;
        *(float4*)&Hs[rr * HPAD + c8] = *(const float4*)&hsrc[rr * DD + c8];
    }
    for (int i = tid; i < 256 * 16; i += 512) {
        int rr = i >> 4, c8 = (i & 15) * 8;
        *(float4*)&Wc[rr * HPAD + c8] = *(const float4*)&g_WcT[rr * DD + c8];
    }
    __syncthreads();

    const int w = tid >> 5, l = tid & 31;
    const int m0 = (w >> 2) * 32;       // 4 m-groups of 32 rows
    const int n0 = (w & 3) * 64;        // 4 n-groups of 64 cats

    float acc[2][8][4];
#pragma unroll
    for (int nt = 0; nt < 8; nt++) {
        float b0 = bcls[n0 + nt * 8 + (l & 3) * 2];
        float b1 = bcls[n0 + nt * 8 + (l & 3) * 2 + 1];
#pragma unroll
        for (int mt = 0; mt < 2; mt++) {
            acc[mt][nt][0] = b0; acc[mt][nt][1] = b1;
            acc[mt][nt][2] = b0; acc[mt][nt][3] = b1;
        }
    }

    const uint32_t hs_u32 = smem_u32(Hs);
    const int arow = m0 + (l & 15);
    const int acol = (l >> 4) * 8;
#pragma unroll
    for (int kt = 0; kt < 8; kt++) {
        uint32_t Af[2][4];
#pragma unroll
        for (int mt = 0; mt < 2; mt++)
            ldsm_x4(Af[mt], hs_u32 + (uint32_t)(((arow + mt * 16) * HPAD + kt * 16 + acol) * 2));
        uint32_t Bf[8][2];
#pragma unroll
        for (int nt = 0; nt < 8; nt++) {
            const __half* wp = &Wc[(n0 + nt * 8 + (l >> 2)) * HPAD + kt * 16 + (l & 3) * 2];
            Bf[nt][0] = *(const uint32_t*)wp;
            Bf[nt][1] = *(const uint32_t*)(wp + 8);
        }
#pragma unroll
        for (int mt = 0; mt < 2; mt++)
#pragma unroll
            for (int nt = 0; nt < 8; nt++) mma16816(acc[mt][nt], Af[mt], Bf[nt]);
    }

    const size_t obase = ((size_t)batch * SEQ + t0) * NCATS;
#pragma unroll
    for (int mt = 0; mt < 2; mt++) {
        const int rrow = m0 + mt * 16 + (l >> 2);
#pragma unroll
        for (int nt = 0; nt < 8; nt++) {
            const int col = n0 + nt * 8 + (l & 3) * 2;
            *(float2*)&out[obase + (size_t)rrow * NCATS + col] =
                make_float2(acc[mt][nt][0], acc[mt][nt][1]);
            *(float2*)&out[obase + (size_t)(rrow + 8) * NCATS + col] =
                make_float2(acc[mt][nt][2], acc[mt][nt][3]);
        }
    }
}

// ---------------- launch ----------------
extern "C" void kernel_launch(void* const* d_in, const int* in_sizes, int n_in,
                              void* d_out, int out_size) {
    const void*  x      = d_in[0];
    const float* emb    = (const float*)d_in[1];
    const float* Wi     = (const float*)d_in[2];
    const float* bi     = (const float*)d_in[3];
    const float* Whrz   = (const float*)d_in[4];
    const float* Whn    = (const float*)d_in[5];
    const float* bhn    = (const float*)d_in[6];
    const float* Wcls   = (const float*)d_in[7];
    const float* bcls   = (const float*)d_in[8];
    const float* initst = (const float*)d_in[9];
    float* out = (float*)d_out;

    const int LOG_SMEM = (128 + 256) * HPAD * (int)sizeof(__half);   // 104448 B
    cudaFuncSetAttribute(logits_kernel, cudaFuncAttributeMaxDynamicSharedMemorySize, LOG_SMEM);

    detect_kernel<<<1, 256>>>((const unsigned int*)x);
    proj_kernel<<<257, DD>>>(emb, Wi, bi);
    prep_wc<<<(NCATS * DD) / 256, 256>>>(Wcls);
    scan_kernel<<<BS / 2, 256>>>((const int*)x, Whrz, Whn, bhn, initst);
    logits_kernel<<<dim3(SEQ / 128, BS), 512, LOG_SMEM>>>(bcls, out);
}